// round 2
// baseline (speedup 1.0000x reference)
#include <cuda_runtime.h>

// Graph_Learn: S[n,i,j] = exp(relu(sum_f |xm[n,i,f]-xm[n,j,f]|*a[f])) / colsum_i
// N=8, T=8 (slice t=4), V=512, F=64. Output (8,512,512) fp32.

#define NB   8
#define TB   8
#define VB   512
#define FB   64
#define JT   32      // j-columns per block
#define IGR  8       // i-groups (threads striding over i)
#define NTHR 256

// smem layout (floats): xm[512*64] | e[512*32] | ps[8*32]
#define SM_XM   0
#define SM_E    (VB*FB)
#define SM_PS   (SM_E + VB*JT)
#define SM_FLOATS (SM_PS + IGR*JT)

__global__ __launch_bounds__(NTHR, 1)
void graph_learn_kernel(const float* __restrict__ x,
                        const float* __restrict__ a,
                        float* __restrict__ out) {
    extern __shared__ float sm[];
    float* xm = sm + SM_XM;   // [512][64]
    float* ev = sm + SM_E;    // [512][32]
    float* ps = sm + SM_PS;   // [8][32]

    const int n   = blockIdx.y;
    const int jc  = blockIdx.x;
    const int tid = threadIdx.x;
    const int jl  = tid & (JT - 1);   // 0..31 (lane within warp)
    const int ig  = tid >> 5;         // 0..7

    // ---- cooperative load of xm[n] (middle time slice), 128 KB via float4 ----
    const float4* __restrict__ xn4 =
        (const float4*)(x + ((size_t)n * TB + TB / 2) * VB * FB);
    float4* xm4 = (float4*)xm;
    for (int k = tid; k < VB * FB / 4; k += NTHR) xm4[k] = xn4[k];

    // ---- a[64] into registers (broadcast LDG.128, L1-resident) ----
    float av[FB];
    #pragma unroll
    for (int k = 0; k < FB / 4; k++) {
        float4 v = __ldg((const float4*)a + k);
        av[4*k+0] = v.x; av[4*k+1] = v.y; av[4*k+2] = v.z; av[4*k+3] = v.w;
    }

    __syncthreads();

    // ---- per-thread j-row into registers ----
    const int j = jc * JT + jl;
    float xj[FB];
    {
        const float4* row = (const float4*)(xm + j * FB);
        #pragma unroll
        for (int k = 0; k < FB / 4; k++) {
            float4 v = row[k];
            xj[4*k+0] = v.x; xj[4*k+1] = v.y; xj[4*k+2] = v.z; xj[4*k+3] = v.w;
        }
    }

    // ---- main loop: each thread handles 64 i-rows for its fixed j ----
    float csum = 0.f;
    for (int ii = ig; ii < VB; ii += IGR) {
        const float4* row = (const float4*)(xm + ii * FB);  // warp-uniform addr -> broadcast
        float a0 = 0.f, a1 = 0.f, a2 = 0.f, a3 = 0.f;       // break FFMA RAW chain
        #pragma unroll
        for (int k = 0; k < FB / 4; k++) {
            float4 v = row[k];
            a0 = fmaf(fabsf(v.x - xj[4*k+0]), av[4*k+0], a0);
            a1 = fmaf(fabsf(v.y - xj[4*k+1]), av[4*k+1], a1);
            a2 = fmaf(fabsf(v.z - xj[4*k+2]), av[4*k+2], a2);
            a3 = fmaf(fabsf(v.w - xj[4*k+3]), av[4*k+3], a3);
        }
        float s = (a0 + a1) + (a2 + a3);
        float e = __expf(fmaxf(s, 0.f));
        ev[ii * JT + jl] = e;   // [i][jl]: consecutive addrs within warp, no conflict
        csum += e;
    }

    // ---- column-sum reduction across the 8 i-groups ----
    ps[ig * JT + jl] = csum;
    __syncthreads();
    float tot = 0.f;
    #pragma unroll
    for (int g = 0; g < IGR; g++) tot += ps[g * JT + jl];
    const float inv = 1.0f / tot;

    // ---- normalize + store (coalesced: warp writes 32 consecutive j) ----
    float* __restrict__ outn = out + (size_t)n * VB * VB;
    for (int ii = ig; ii < VB; ii += IGR) {
        outn[(size_t)ii * VB + j] = ev[ii * JT + jl] * inv;
    }
}

extern "C" void kernel_launch(void* const* d_in, const int* in_sizes, int n_in,
                              void* d_out, int out_size) {
    const float* x = (const float*)d_in[0];   // (8,8,512,64) fp32
    const float* a = (const float*)d_in[1];   // (64,1) fp32
    float* out = (float*)d_out;               // (8,512,512) fp32

    const int smem_bytes = SM_FLOATS * (int)sizeof(float);  // ~193 KB
    cudaFuncSetAttribute(graph_learn_kernel,
                         cudaFuncAttributeMaxDynamicSharedMemorySize, smem_bytes);

    dim3 grid(VB / JT, NB);   // (16, 8) = 128 blocks
    graph_learn_kernel<<<grid, NTHR, smem_bytes>>>(x, a, out);
}